// round 16
// baseline (speedup 1.0000x reference)
#include <cuda_runtime.h>

// Fixed problem shape
#define BB 4
#define CC 19
#define HH 256
#define WW 256
#define HW (HH * WW)
#define CHW (CC * HW)
#define RAD 10
#define TS 32
#define EW (TS + 2 * RAD)   // 52
#define NBLK2 256           // K2 block count (64 tiles x 4 images)

// Scratch (device globals; self-resetting each replay)
__device__ float g_ent[BB * HW];
__device__ float g_kl[BB * HW];
__device__ unsigned char g_fg[BB * HW];
__device__ int g_entmax[BB];       // entropy > 0 -> int atomicMax is order-preserving
__device__ double g_acc[BB][4];    // per-image: A=Σb·kl, B=Σb·kl·ent, C=Σb, D=Σb·ent
__device__ unsigned int g_done;    // K2 completion counter

// ---------------------------------------------------------------------------
// K1: 1 pixel/thread, coalesced, LTS-bound (proven R7 body).
// Ends with cudaTriggerProgrammaticLaunchCompletion so the dependent K2's
// grid dispatch overlaps K1's tail (PDL).
// ---------------------------------------------------------------------------
__global__ void __launch_bounds__(256) k1_channelwise(
    const float* __restrict__ student, const float* __restrict__ teacher)
{
    const int b = blockIdx.y;
    const int p = blockIdx.x * 256 + threadIdx.x;
    const size_t base = (size_t)b * CHW + p;

    float Z = 0.f, S = 0.f, Tt = 0.f, Zs = 0.f;
    float t0, mx = -1e30f;
#pragma unroll
    for (int c = 0; c < CC; c++) {
        float tv = __ldg(teacher + base + (size_t)c * HW) * 0.25f;
        float sv = __ldg(student + base + (size_t)c * HW) * 0.25f;
        float e = __expf(tv);
        Z += e;
        S = fmaf(e, tv, S);
        Tt = fmaf(e, sv, Tt);
        Zs += __expf(sv);
        if (c == 0) t0 = tv;
        else        mx = fmaxf(mx, tv);
    }
    const float lZ = __logf(Z);
    const float ent = lZ - S / Z;
    const float kl = (S - Tt) / Z - lZ + __logf(Zs);

    const int idx = b * HW + p;
    g_ent[idx] = ent;
    g_kl[idx] = kl;
    g_fg[idx] = (mx > t0) ? 1 : 0;   // argmax != 0 (ties -> class 0)

    float entm = ent;
#pragma unroll
    for (int o = 16; o > 0; o >>= 1)
        entm = fmaxf(entm, __shfl_xor_sync(0xFFFFFFFF, entm, o));
    __shared__ float smax[8];
    if ((threadIdx.x & 31) == 0) smax[threadIdx.x >> 5] = entm;
    __syncthreads();
    if (threadIdx.x == 0) {
        float m = smax[0];
#pragma unroll
        for (int w = 1; w < 8; w++) m = fmaxf(m, smax[w]);
        atomicMax(&g_entmax[b], __float_as_int(m));
    }

    // PDL: this block's work is done — let the dependent kernel start
    // dispatching (memory visibility is handled by K2's grid sync).
    cudaTriggerProgrammaticLaunchCompletion();
}

// ---------------------------------------------------------------------------
// K2: bounded EDT + weights + finalize (exact R7 body). Launched with
// programmatic stream serialization: blocks may start during K1's tail;
// cudaGridDependencySynchronize() blocks until K1 fully completes (and its
// memory is visible) before any K1 output is read.
// ---------------------------------------------------------------------------
__global__ void __launch_bounds__(1024) k2_edt_weights(float* __restrict__ out)
{
    const int b   = blockIdx.y;
    const int i0  = (blockIdx.x >> 3) * TS;
    const int j0  = (blockIdx.x & 7) * TS;
    const int tid = threadIdx.x;
    const int ty  = tid >> 5;          // tile row 0..31
    const int tx  = tid & 31;          // tile col 0..31

    // Wait for K1 completion + memory visibility (overlaps dispatch with K1 tail)
    cudaGridDependencySynchronize();

    // prefetch ent/kl (coalesced; L2-resident) — starts latency early
    const int pidx = b * HW + (i0 + ty) * WW + j0 + tx;
    const float entv = __ldg(g_ent + pidx);
    const float klv  = __ldg(g_kl + pidx);

    __shared__ unsigned char sfg[EW][56];  // fg halo: col cc = global j0-12+cc
    __shared__ unsigned char svv[TS][56];  // vertical min-d^2

    // fg halo: 52 rows x 14 aligned u32 words (single step, tid < 728)
    if (tid < EW * 14) {
        int r = tid / 14, k = tid - r * 14;
        int gi = i0 - RAD + r;
        int g0 = j0 - 12 + 4 * k;          // j0 % 32 == 0 -> g0 % 4 == 0
        unsigned int word = 0;
        if (gi >= 0 && gi < HH) {
            const unsigned char* rowp = g_fg + b * HW + gi * WW;
            if (g0 >= 0 && g0 + 3 < WW) {
                word = *(const unsigned int*)(rowp + g0);
            } else {
#pragma unroll
                for (int bb = 0; bb < 4; bb++) {
                    int gj = g0 + bb;
                    if (gj >= 0 && gj < WW)
                        word |= (unsigned int)rowp[gj] << (8 * bb);
                }
            }
        }
        *(unsigned int*)&sfg[r][4 * k] = word;
    }
    __syncthreads();

    // vertical 21-tap min, byte SIMD (term = 200 - fg*(200-d^2)), 2 chains
    if (tid < TS * 14) {
        int r = tid / 14, wc = (tid - r * 14) * 4;
        unsigned int va = 0xC8C8C8C8u, vb = 0xC8C8C8C8u;
#pragma unroll
        for (int dr = 0; dr < 21; dr += 2) {
            unsigned int f4 = *(const unsigned int*)&sfg[r + dr][wc];
            int d = dr - RAD;
            va = __vminu4(va, 0xC8C8C8C8u - f4 * (unsigned int)(200 - d * d));
        }
#pragma unroll
        for (int dr = 1; dr < 21; dr += 2) {
            unsigned int f4 = *(const unsigned int*)&sfg[r + dr][wc];
            int d = dr - RAD;
            vb = __vminu4(vb, 0xC8C8C8C8u - f4 * (unsigned int)(200 - d * d));
        }
        *(unsigned int*)&svv[r][wc] = __vminu4(va, vb);
    }
    __syncthreads();

    // horizontal 21-tap min: independent byte-LDS, 3 split chains
    // pixel col tx -> smem cc = tx+12; taps tx+2 .. tx+22
    int m0 = 300, m1 = 300, m2 = 300;
#pragma unroll
    for (int s = 0; s < 7; s++) {
        int dd = s - RAD;
        m0 = min(m0, dd * dd + (int)svv[ty][tx + 2 + s]);
    }
#pragma unroll
    for (int s = 7; s < 14; s++) {
        int dd = s - RAD;
        m1 = min(m1, dd * dd + (int)svv[ty][tx + 2 + s]);
    }
#pragma unroll
    for (int s = 14; s < 21; s++) {
        int dd = s - RAD;
        m2 = min(m2, dd * dd + (int)svv[ty][tx + 2 + s]);
    }
    const int d2 = min(m0, min(m1, m2));

    // base weight; conf = 1 - 0.9*ent/Em is linear in ent -> accumulate
    // A=Σbw·kl, B=Σbw·kl·ent, C=Σbw, D=Σbw·ent; Em applied at finalize.
    float a0 = 0.f, a1 = 0.f, a2 = 0.f, a3 = 0.f;
    if (d2 <= RAD * RAD) {
        float wd = __expf((float)d2 * (-1.0f / 50.0f));   // 2*sigma^2 = 50
        float bnd = 0.f;
        if (sfg[ty + RAD][tx + 12]) {
            bool er = sfg[ty + RAD - 1][tx + 12] && sfg[ty + RAD + 1][tx + 12]
                   && sfg[ty + RAD][tx + 11] && sfg[ty + RAD][tx + 13];
            if (!er) bnd = 1.f;
        }
        float bw = wd * (1.f + bnd);
        a0 = bw * klv;
        a1 = bw * klv * entv;
        a2 = bw;
        a3 = bw * entv;
    }

    // block reduce 4 sums
#pragma unroll
    for (int o = 16; o > 0; o >>= 1) {
        a0 += __shfl_xor_sync(0xFFFFFFFF, a0, o);
        a1 += __shfl_xor_sync(0xFFFFFFFF, a1, o);
        a2 += __shfl_xor_sync(0xFFFFFFFF, a2, o);
        a3 += __shfl_xor_sync(0xFFFFFFFF, a3, o);
    }
    __shared__ float red[4][32];
    if ((tid & 31) == 0) {
        red[0][tid >> 5] = a0; red[1][tid >> 5] = a1;
        red[2][tid >> 5] = a2; red[3][tid >> 5] = a3;
    }
    __syncthreads();

    if (tid < 32) {
        float s0 = red[0][tid], s1 = red[1][tid], s2 = red[2][tid], s3 = red[3][tid];
#pragma unroll
        for (int o = 16; o > 0; o >>= 1) {
            s0 += __shfl_xor_sync(0xFFFFFFFF, s0, o);
            s1 += __shfl_xor_sync(0xFFFFFFFF, s1, o);
            s2 += __shfl_xor_sync(0xFFFFFFFF, s2, o);
            s3 += __shfl_xor_sync(0xFFFFFFFF, s3, o);
        }
        if (tid == 0) {
            atomicAdd(&g_acc[b][0], (double)s0);
            atomicAdd(&g_acc[b][1], (double)s1);
            atomicAdd(&g_acc[b][2], (double)s2);
            atomicAdd(&g_acc[b][3], (double)s3);
            __threadfence();
            unsigned int t = atomicAdd(&g_done, 1u);
            if (t == NBLK2 - 1) {   // last block: finalize + reset for next replay
                double num = 0.0, den = 0.0;
#pragma unroll
                for (int bb = 0; bb < BB; bb++) {
                    double Em = (double)__int_as_float(g_entmax[bb]) + 1e-8;
                    double A  = g_acc[bb][0], Bm = g_acc[bb][1];
                    double Cc = g_acc[bb][2], D  = g_acc[bb][3];
                    num += A - 0.9 * Bm / Em;
                    den += Cc - 0.9 * D / Em;
                    g_acc[bb][0] = 0.0; g_acc[bb][1] = 0.0;
                    g_acc[bb][2] = 0.0; g_acc[bb][3] = 0.0;
                    g_entmax[bb] = 0;
                }
                out[0] = (float)(16.0 * num / (den + 1e-8));
                atomicExch(&g_done, 0u);
            }
        }
    }
}

extern "C" void kernel_launch(void* const* d_in, const int* in_sizes, int n_in,
                              void* d_out, int out_size)
{
    const float* student = (const float*)d_in[0];
    const float* teacher = (const float*)d_in[1];
    float* out = (float*)d_out;

    // K1: normal launch on the capture (default) stream
    k1_channelwise<<<dim3(HW / 256, BB), 256>>>(student, teacher);

    // K2: programmatic dependent launch — dispatch overlaps K1's tail
    cudaLaunchConfig_t cfg = {};
    cfg.gridDim = dim3(64, BB);
    cfg.blockDim = dim3(1024);
    cfg.dynamicSmemBytes = 0;
    cfg.stream = 0;
    cudaLaunchAttribute attr[1];
    attr[0].id = cudaLaunchAttributeProgrammaticStreamSerialization;
    attr[0].val.programmaticStreamSerializationAllowed = 1;
    cfg.attrs = attr;
    cfg.numAttrs = 1;
    cudaLaunchKernelEx(&cfg, k2_edt_weights, out);
}

// round 17
// speedup vs baseline: 1.0122x; 1.0122x over previous
#include <cuda_runtime.h>

// Fixed problem shape
#define BB 4
#define CC 19
#define HH 256
#define WW 256
#define HW (HH * WW)
#define CHW (CC * HW)
#define RAD 10
#define TS 32
#define EW (TS + 2 * RAD)   // 52
#define NBLK2 256           // K2 block count (64 tiles x 4 images)

// Scratch (device globals; self-resetting each replay)
__device__ float g_ent[BB * HW];
__device__ float g_kl[BB * HW];
__device__ unsigned char g_fg[BB * HW];
__device__ int g_entmax[BB];       // entropy > 0 -> int atomicMax is order-preserving
__device__ double g_acc[BB][4];    // per-image: A=Σb·kl, B=Σb·kl·ent, C=Σb, D=Σb·ent
__device__ unsigned int g_done;    // K2 completion counter

// ---------------------------------------------------------------------------
// K1: 2 pixels/thread via float2 — half the LDG instructions of the proven
// R7 version, two independent accumulation chains (double per-thread MLP).
// Same occupancy class (512x4 blocks, 256 threads = ~55 warps/SM).
// ---------------------------------------------------------------------------
__global__ void __launch_bounds__(256) k1_channelwise(
    const float* __restrict__ student, const float* __restrict__ teacher)
{
    const int b = blockIdx.y;
    const int p = (blockIdx.x * 256 + threadIdx.x) * 2;
    const size_t base = (size_t)b * CHW + p;

    float Z0 = 0.f, S0 = 0.f, T0 = 0.f, Q0 = 0.f;
    float Z1 = 0.f, S1 = 0.f, T1 = 0.f, Q1 = 0.f;
    float t00, t01, mx0 = -1e30f, mx1 = -1e30f;

#pragma unroll
    for (int c = 0; c < CC; c++) {
        float2 t2 = *(const float2*)(teacher + base + (size_t)c * HW);
        float2 s2 = *(const float2*)(student + base + (size_t)c * HW);
        float tv0 = t2.x * 0.25f, tv1 = t2.y * 0.25f;
        float sv0 = s2.x * 0.25f, sv1 = s2.y * 0.25f;
        float e0 = __expf(tv0), e1 = __expf(tv1);
        Z0 += e0;               Z1 += e1;
        S0 = fmaf(e0, tv0, S0); S1 = fmaf(e1, tv1, S1);
        T0 = fmaf(e0, sv0, T0); T1 = fmaf(e1, sv1, T1);
        Q0 += __expf(sv0);      Q1 += __expf(sv1);
        if (c == 0) { t00 = tv0; t01 = tv1; }
        else { mx0 = fmaxf(mx0, tv0); mx1 = fmaxf(mx1, tv1); }
    }

    const float lZ0 = __logf(Z0), lZ1 = __logf(Z1);
    const float ent0 = lZ0 - S0 / Z0, ent1 = lZ1 - S1 / Z1;
    const float kl0 = (S0 - T0) / Z0 - lZ0 + __logf(Q0);
    const float kl1 = (S1 - T1) / Z1 - lZ1 + __logf(Q1);

    const int idx = b * HW + p;
    *(float2*)(g_ent + idx) = make_float2(ent0, ent1);
    *(float2*)(g_kl + idx)  = make_float2(kl0, kl1);
    g_fg[idx]     = (mx0 > t00) ? 1 : 0;   // argmax != 0 (ties -> class 0)
    g_fg[idx + 1] = (mx1 > t01) ? 1 : 0;

    // block entropy max -> atomicMax per image
    float entm = fmaxf(ent0, ent1);
#pragma unroll
    for (int o = 16; o > 0; o >>= 1)
        entm = fmaxf(entm, __shfl_xor_sync(0xFFFFFFFF, entm, o));
    __shared__ float smax[8];
    if ((threadIdx.x & 31) == 0) smax[threadIdx.x >> 5] = entm;
    __syncthreads();
    if (threadIdx.x == 0) {
        float m = smax[0];
#pragma unroll
        for (int w = 1; w < 8; w++) m = fmaxf(m, smax[w]);
        atomicMax(&g_entmax[b], __float_as_int(m));
    }
}

// ---------------------------------------------------------------------------
// K2: bounded EDT + weights + finalize — EXACT R7 body (proven best: 32 regs,
// 1024 threads, 69% occ, 9.9 us). Do not touch.
// ---------------------------------------------------------------------------
__global__ void __launch_bounds__(1024) k2_edt_weights(float* __restrict__ out)
{
    const int b   = blockIdx.y;
    const int i0  = (blockIdx.x >> 3) * TS;
    const int j0  = (blockIdx.x & 7) * TS;
    const int tid = threadIdx.x;
    const int ty  = tid >> 5;          // tile row 0..31
    const int tx  = tid & 31;          // tile col 0..31

    // prefetch ent/kl (coalesced; L2-resident) — starts latency early
    const int pidx = b * HW + (i0 + ty) * WW + j0 + tx;
    const float entv = __ldg(g_ent + pidx);
    const float klv  = __ldg(g_kl + pidx);

    __shared__ unsigned char sfg[EW][56];  // fg halo: col cc = global j0-12+cc
    __shared__ unsigned char svv[TS][56];  // vertical min-d^2

    // fg halo: 52 rows x 14 aligned u32 words (single step, tid < 728)
    if (tid < EW * 14) {
        int r = tid / 14, k = tid - r * 14;
        int gi = i0 - RAD + r;
        int g0 = j0 - 12 + 4 * k;          // j0 % 32 == 0 -> g0 % 4 == 0
        unsigned int word = 0;
        if (gi >= 0 && gi < HH) {
            const unsigned char* rowp = g_fg + b * HW + gi * WW;
            if (g0 >= 0 && g0 + 3 < WW) {
                word = *(const unsigned int*)(rowp + g0);
            } else {
#pragma unroll
                for (int bb = 0; bb < 4; bb++) {
                    int gj = g0 + bb;
                    if (gj >= 0 && gj < WW)
                        word |= (unsigned int)rowp[gj] << (8 * bb);
                }
            }
        }
        *(unsigned int*)&sfg[r][4 * k] = word;
    }
    __syncthreads();

    // vertical 21-tap min, byte SIMD (term = 200 - fg*(200-d^2)), 2 chains
    if (tid < TS * 14) {
        int r = tid / 14, wc = (tid - r * 14) * 4;
        unsigned int va = 0xC8C8C8C8u, vb = 0xC8C8C8C8u;
#pragma unroll
        for (int dr = 0; dr < 21; dr += 2) {
            unsigned int f4 = *(const unsigned int*)&sfg[r + dr][wc];
            int d = dr - RAD;
            va = __vminu4(va, 0xC8C8C8C8u - f4 * (unsigned int)(200 - d * d));
        }
#pragma unroll
        for (int dr = 1; dr < 21; dr += 2) {
            unsigned int f4 = *(const unsigned int*)&sfg[r + dr][wc];
            int d = dr - RAD;
            vb = __vminu4(vb, 0xC8C8C8C8u - f4 * (unsigned int)(200 - d * d));
        }
        *(unsigned int*)&svv[r][wc] = __vminu4(va, vb);
    }
    __syncthreads();

    // horizontal 21-tap min: independent byte-LDS, 3 split chains
    // pixel col tx -> smem cc = tx+12; taps tx+2 .. tx+22
    int m0 = 300, m1 = 300, m2 = 300;
#pragma unroll
    for (int s = 0; s < 7; s++) {
        int dd = s - RAD;
        m0 = min(m0, dd * dd + (int)svv[ty][tx + 2 + s]);
    }
#pragma unroll
    for (int s = 7; s < 14; s++) {
        int dd = s - RAD;
        m1 = min(m1, dd * dd + (int)svv[ty][tx + 2 + s]);
    }
#pragma unroll
    for (int s = 14; s < 21; s++) {
        int dd = s - RAD;
        m2 = min(m2, dd * dd + (int)svv[ty][tx + 2 + s]);
    }
    const int d2 = min(m0, min(m1, m2));

    // base weight; conf = 1 - 0.9*ent/Em is linear in ent -> accumulate
    // A=Σbw·kl, B=Σbw·kl·ent, C=Σbw, D=Σbw·ent; Em applied at finalize.
    float a0 = 0.f, a1 = 0.f, a2 = 0.f, a3 = 0.f;
    if (d2 <= RAD * RAD) {
        float wd = __expf((float)d2 * (-1.0f / 50.0f));   // 2*sigma^2 = 50
        float bnd = 0.f;
        if (sfg[ty + RAD][tx + 12]) {
            bool er = sfg[ty + RAD - 1][tx + 12] && sfg[ty + RAD + 1][tx + 12]
                   && sfg[ty + RAD][tx + 11] && sfg[ty + RAD][tx + 13];
            if (!er) bnd = 1.f;
        }
        float bw = wd * (1.f + bnd);
        a0 = bw * klv;
        a1 = bw * klv * entv;
        a2 = bw;
        a3 = bw * entv;
    }

    // block reduce 4 sums
#pragma unroll
    for (int o = 16; o > 0; o >>= 1) {
        a0 += __shfl_xor_sync(0xFFFFFFFF, a0, o);
        a1 += __shfl_xor_sync(0xFFFFFFFF, a1, o);
        a2 += __shfl_xor_sync(0xFFFFFFFF, a2, o);
        a3 += __shfl_xor_sync(0xFFFFFFFF, a3, o);
    }
    __shared__ float red[4][32];
    if ((tid & 31) == 0) {
        red[0][tid >> 5] = a0; red[1][tid >> 5] = a1;
        red[2][tid >> 5] = a2; red[3][tid >> 5] = a3;
    }
    __syncthreads();

    if (tid < 32) {
        float s0 = red[0][tid], s1 = red[1][tid], s2 = red[2][tid], s3 = red[3][tid];
#pragma unroll
        for (int o = 16; o > 0; o >>= 1) {
            s0 += __shfl_xor_sync(0xFFFFFFFF, s0, o);
            s1 += __shfl_xor_sync(0xFFFFFFFF, s1, o);
            s2 += __shfl_xor_sync(0xFFFFFFFF, s2, o);
            s3 += __shfl_xor_sync(0xFFFFFFFF, s3, o);
        }
        if (tid == 0) {
            atomicAdd(&g_acc[b][0], (double)s0);
            atomicAdd(&g_acc[b][1], (double)s1);
            atomicAdd(&g_acc[b][2], (double)s2);
            atomicAdd(&g_acc[b][3], (double)s3);
            __threadfence();
            unsigned int t = atomicAdd(&g_done, 1u);
            if (t == NBLK2 - 1) {   // last block: finalize + reset for next replay
                double num = 0.0, den = 0.0;
#pragma unroll
                for (int bb = 0; bb < BB; bb++) {
                    double Em = (double)__int_as_float(g_entmax[bb]) + 1e-8;
                    num += g_acc[bb][0] - 0.9 * g_acc[bb][1] / Em;
                    den += g_acc[bb][2] - 0.9 * g_acc[bb][3] / Em;
                    g_acc[bb][0] = 0.0; g_acc[bb][1] = 0.0;
                    g_acc[bb][2] = 0.0; g_acc[bb][3] = 0.0;
                    g_entmax[bb] = 0;
                }
                out[0] = (float)(16.0 * num / (den + 1e-8));
                atomicExch(&g_done, 0u);
            }
        }
    }
}

extern "C" void kernel_launch(void* const* d_in, const int* in_sizes, int n_in,
                              void* d_out, int out_size)
{
    const float* student = (const float*)d_in[0];
    const float* teacher = (const float*)d_in[1];
    float* out = (float*)d_out;

    k1_channelwise<<<dim3(HW / 512, BB), 256>>>(student, teacher);
    k2_edt_weights<<<dim3(64, BB), 1024>>>(out);
}